// round 1
// baseline (speedup 1.0000x reference)
#include <cuda_runtime.h>

// Skip-gram negative-sampling loss (PennSkipGramModel).
// Inputs (metadata order):
//   0: u_l_weight  [100000*128] f32
//   1: u_r_weight  [100000*128] f32
//   2: v_l_weight  [100000*128] f32
//   3: v_r_weight  [100000*128] f32
//   4: pos_u       [B]     i32
//   5: pos_v_l     [B]     i32
//   6: pos_v_r     [B]     i32
//   7: neg_v_l     [B*K]   i32
//   8: neg_v_r     [B*K]   i32
// Output: scalar f32 mean loss.

#define HALF 128
#define KNEG 5
#define BLOCK_THREADS 256
#define WARPS_PER_BLOCK (BLOCK_THREADS / 32)
#define MAX_PARTIALS 16384

__device__ float g_partials[MAX_PARTIALS];

__device__ __forceinline__ float warp_reduce_sum(float v) {
    v += __shfl_xor_sync(0xffffffffu, v, 16);
    v += __shfl_xor_sync(0xffffffffu, v, 8);
    v += __shfl_xor_sync(0xffffffffu, v, 4);
    v += __shfl_xor_sync(0xffffffffu, v, 2);
    v += __shfl_xor_sync(0xffffffffu, v, 1);
    return v;
}

// softplus(x) = log(1 + exp(x)); inputs are pre-clipped to [-10, 10] so
// exp(x) <= 22026 -> no overflow, log1pf keeps accuracy near 0.
__device__ __forceinline__ float softplus_clipped(float x) {
    return log1pf(expf(x));
}

__device__ __forceinline__ float clip10(float x) {
    return fminf(fmaxf(x, -10.0f), 10.0f);
}

__device__ __forceinline__ float dot4(float4 a, float4 b) {
    return fmaf(a.x, b.x, fmaf(a.y, b.y, fmaf(a.z, b.z, a.w * b.w)));
}

__global__ void skipgram_loss_kernel(
    const float* __restrict__ u_l, const float* __restrict__ u_r,
    const float* __restrict__ v_l, const float* __restrict__ v_r,
    const int* __restrict__ pos_u,
    const int* __restrict__ pos_v_l, const int* __restrict__ pos_v_r,
    const int* __restrict__ neg_v_l, const int* __restrict__ neg_v_r,
    int batch)
{
    const int lane = threadIdx.x & 31;
    const int warp_in_block = threadIdx.x >> 5;
    const int b = blockIdx.x * WARPS_PER_BLOCK + warp_in_block;

    float acc = 0.0f;

    if (b < batch) {
        // ---- gather all indices first (lane-uniform loads) ----
        const int iu  = pos_u[b];
        const int ipl = pos_v_l[b];
        const int ipr = pos_v_r[b];
        int inl[KNEG], inr[KNEG];
#pragma unroll
        for (int k = 0; k < KNEG; k++) inl[k] = neg_v_l[b * KNEG + k];
#pragma unroll
        for (int k = 0; k < KNEG; k++) inr[k] = neg_v_r[b * KNEG + k];

        const int off = lane * 4;

        // ---- front-batch all 14 row loads (float4 per lane) for MLP ----
        const float4 ul  = *(const float4*)(u_l + (size_t)iu  * HALF + off);
        const float4 ur  = *(const float4*)(u_r + (size_t)iu  * HALF + off);
        const float4 vpl = *(const float4*)(v_l + (size_t)ipl * HALF + off);
        const float4 vpr = *(const float4*)(v_r + (size_t)ipr * HALF + off);
        float4 vnl[KNEG], vnr[KNEG];
#pragma unroll
        for (int k = 0; k < KNEG; k++)
            vnl[k] = *(const float4*)(v_l + (size_t)inl[k] * HALF + off);
#pragma unroll
        for (int k = 0; k < KNEG; k++)
            vnr[k] = *(const float4*)(v_r + (size_t)inr[k] * HALF + off);

        // ---- positive scores: -logsigmoid(d) = softplus(-d) ----
        float dl = warp_reduce_sum(dot4(ul, vpl));
        float dr = warp_reduce_sum(dot4(ur, vpr));
        acc += softplus_clipped(-clip10(dl));
        acc += softplus_clipped(-clip10(dr));

        // ---- negative scores: -logsigmoid(-d) = softplus(d) ----
#pragma unroll
        for (int k = 0; k < KNEG; k++) {
            float d = warp_reduce_sum(dot4(ul, vnl[k]));
            acc += softplus_clipped(clip10(d));
        }
#pragma unroll
        for (int k = 0; k < KNEG; k++) {
            float d = warp_reduce_sum(dot4(ur, vnr[k]));
            acc += softplus_clipped(clip10(d));
        }
    }

    // ---- block reduce (lane 0 of each warp holds acc; all lanes equal) ----
    __shared__ float s_warp[WARPS_PER_BLOCK];
    if (lane == 0) s_warp[warp_in_block] = acc;
    __syncthreads();

    if (warp_in_block == 0) {
        float v = (lane < WARPS_PER_BLOCK) ? s_warp[lane] : 0.0f;
#pragma unroll
        for (int s = WARPS_PER_BLOCK / 2; s > 0; s >>= 1)
            v += __shfl_xor_sync(0xffffffffu, v, s);
        if (lane == 0) g_partials[blockIdx.x] = v;
    }
}

__global__ void final_reduce_kernel(float* __restrict__ out, int nparts, float inv_b)
{
    __shared__ float s[BLOCK_THREADS];
    float a = 0.0f;
    for (int i = threadIdx.x; i < nparts; i += BLOCK_THREADS)
        a += g_partials[i];
    s[threadIdx.x] = a;
    __syncthreads();
#pragma unroll
    for (int st = BLOCK_THREADS / 2; st > 0; st >>= 1) {
        if (threadIdx.x < st) s[threadIdx.x] += s[threadIdx.x + st];
        __syncthreads();
    }
    if (threadIdx.x == 0) out[0] = s[0] * inv_b;
}

extern "C" void kernel_launch(void* const* d_in, const int* in_sizes, int n_in,
                              void* d_out, int out_size)
{
    const float* u_l = (const float*)d_in[0];
    const float* u_r = (const float*)d_in[1];
    const float* v_l = (const float*)d_in[2];
    const float* v_r = (const float*)d_in[3];
    const int* pos_u   = (const int*)d_in[4];
    const int* pos_v_l = (const int*)d_in[5];
    const int* pos_v_r = (const int*)d_in[6];
    const int* neg_v_l = (const int*)d_in[7];
    const int* neg_v_r = (const int*)d_in[8];

    const int batch = in_sizes[4];
    const int nblocks = (batch + WARPS_PER_BLOCK - 1) / WARPS_PER_BLOCK;
    // nblocks = 8192 for B=65536; MAX_PARTIALS=16384 headroom.

    skipgram_loss_kernel<<<nblocks, BLOCK_THREADS>>>(
        u_l, u_r, v_l, v_r, pos_u, pos_v_l, pos_v_r, neg_v_l, neg_v_r, batch);

    final_reduce_kernel<<<1, BLOCK_THREADS>>>(
        (float*)d_out, nblocks, 1.0f / (float)batch);
}